// round 1
// baseline (speedup 1.0000x reference)
#include <cuda_runtime.h>
#include <cstdint>
#include <cstddef>

#define D 128
#define TILE_ROWS 64
#define NTHREADS 256

// Scratch for message-transformed features (allocation-free rule: device globals)
__device__ float g_U2I[100000 * 128];  // user_features @ W_u2i^T  (no bias)
__device__ float g_I2U[50000 * 128];   // item_features @ W_i2u^T  (no bias)

__device__ __forceinline__ unsigned long long pack2(float a, float b) {
    unsigned long long r;
    asm("mov.b64 %0, {%1, %2};" : "=l"(r) : "f"(a), "f"(b));
    return r;
}
__device__ __forceinline__ void fma2(unsigned long long& acc, unsigned long long x, unsigned long long w) {
    asm("fma.rn.f32x2 %0, %1, %2, %0;" : "+l"(acc) : "l"(x), "l"(w));
}
__device__ __forceinline__ float2 unpack2(unsigned long long v) {
    float2 f;
    asm("mov.b64 {%0, %1}, %2;" : "=f"(f.x), "=f"(f.y) : "l"(v));
    return f;
}

// Persistent dual-output GEMM:
//   Yself[n, 0:128] = X[n] @ Wa^T + ba
//   Ymsg [n, 0:128] = X[n] @ Wb^T          (bias folded in at scatter time)
// smem: Wt[128][256] (k-major, Wa outs 0..127, Wb outs 128..255) + Xs[64][128]
extern __shared__ float smem_dyn[];

__global__ __launch_bounds__(NTHREADS, 1)
void gemm_dual(const float* __restrict__ X, int nrows,
               const float* __restrict__ Wa, const float* __restrict__ ba,
               const float* __restrict__ Wb,
               float* __restrict__ Yself, float* __restrict__ Ymsg)
{
    float* Wt = smem_dyn;             // 128*256 floats
    float* Xs = smem_dyn + 128 * 256; // 64*128 floats
    const int tid = threadIdx.x;
    const int c = tid & 31;           // lane: owns outputs [c*4, c*4+3] of each half
    const int rbase = (tid >> 5) * 8; // warp: owns 8 rows of the tile

    // Load W transposed into smem. Consecutive threads -> consecutive o
    // (conflict-free smem stores; strided global reads hit L2, one-time cost).
    for (int i = tid; i < 128 * 128; i += NTHREADS) {
        int k = i >> 7, o = i & 127;
        Wt[k * 256 + o]       = Wa[o * 128 + k];
        Wt[k * 256 + 128 + o] = Wb[o * 128 + k];
    }
    const float4 bias = *(const float4*)&ba[c * 4];

    const int ntiles = (nrows + TILE_ROWS - 1) / TILE_ROWS;

    for (int tile = blockIdx.x; tile < ntiles; tile += gridDim.x) {
        const int row0 = tile * TILE_ROWS;
        __syncthreads();  // previous tile's readers done (also covers W load on iter 0)

        // Cooperative X tile load (zero-pad tail rows)
        for (int i = tid; i < TILE_ROWS * 32; i += NTHREADS) {
            int r = i >> 5, q = i & 31;
            float4 v = make_float4(0.f, 0.f, 0.f, 0.f);
            if (row0 + r < nrows)
                v = *(const float4*)&X[(size_t)(row0 + r) * D + q * 4];
            *(float4*)&Xs[r * D + q * 4] = v;
        }
        __syncthreads();

        unsigned long long accA[8][2], accB[8][2];
        #pragma unroll
        for (int r = 0; r < 8; r++) {
            accA[r][0] = 0ull; accA[r][1] = 0ull;
            accB[r][0] = 0ull; accB[r][1] = 0ull;
        }

        #pragma unroll 4
        for (int k = 0; k < D; k += 4) {
            ulonglong2 wA[4], wB[4];
            #pragma unroll
            for (int j = 0; j < 4; j++) {
                wA[j] = *(const ulonglong2*)&Wt[(k + j) * 256 + c * 4];
                wB[j] = *(const ulonglong2*)&Wt[(k + j) * 256 + 128 + c * 4];
            }
            #pragma unroll
            for (int r = 0; r < 8; r++) {
                const float4 xv = *(const float4*)&Xs[(rbase + r) * D + k];
                unsigned long long xx;
                xx = pack2(xv.x, xv.x);
                fma2(accA[r][0], xx, wA[0].x); fma2(accA[r][1], xx, wA[0].y);
                fma2(accB[r][0], xx, wB[0].x); fma2(accB[r][1], xx, wB[0].y);
                xx = pack2(xv.y, xv.y);
                fma2(accA[r][0], xx, wA[1].x); fma2(accA[r][1], xx, wA[1].y);
                fma2(accB[r][0], xx, wB[1].x); fma2(accB[r][1], xx, wB[1].y);
                xx = pack2(xv.z, xv.z);
                fma2(accA[r][0], xx, wA[2].x); fma2(accA[r][1], xx, wA[2].y);
                fma2(accB[r][0], xx, wB[2].x); fma2(accB[r][1], xx, wB[2].y);
                xx = pack2(xv.w, xv.w);
                fma2(accA[r][0], xx, wA[3].x); fma2(accA[r][1], xx, wA[3].y);
                fma2(accB[r][0], xx, wB[3].x); fma2(accB[r][1], xx, wB[3].y);
            }
        }

        #pragma unroll
        for (int r = 0; r < 8; r++) {
            const int row = row0 + rbase + r;
            if (row < nrows) {
                float2 a0 = unpack2(accA[r][0]), a1 = unpack2(accA[r][1]);
                *(float4*)&Yself[(size_t)row * D + c * 4] =
                    make_float4(a0.x + bias.x, a0.y + bias.y, a1.x + bias.z, a1.y + bias.w);
                float2 b0 = unpack2(accB[r][0]), b1 = unpack2(accB[r][1]);
                *(float4*)&Ymsg[(size_t)row * D + c * 4] =
                    make_float4(b0.x, b0.y, b1.x, b1.y);
            }
        }
    }
}

// One warp per edge: gather transformed row, add bias, vector-reduce onto target.
__global__ void scatter_k(const int* __restrict__ eu, const int* __restrict__ ei,
                          const float* __restrict__ bu2i, const float* __restrict__ bi2u,
                          float* __restrict__ user_out, float* __restrict__ item_out, int E)
{
    const int lane = threadIdx.x & 31;
    const int e = (blockIdx.x * blockDim.x + threadIdx.x) >> 5;
    if (e >= E) return;
    const int off = lane * 4;
    const float4 bu = *(const float4*)&bu2i[off];
    const float4 bi = *(const float4*)&bi2u[off];

    const int u  = __ldg(&eu[e]);
    const int it = __ldg(&ei[e]);

    // user -> item
    float4 mu = *(const float4*)&g_U2I[(size_t)u * D + off];
    float* dstI = &item_out[(size_t)it * D + off];
    asm volatile("red.global.add.v4.f32 [%0], {%1,%2,%3,%4};" ::
        "l"(dstI),
        "f"(mu.x + bu.x), "f"(mu.y + bu.y), "f"(mu.z + bu.z), "f"(mu.w + bu.w)
        : "memory");

    // item -> user
    float4 mi = *(const float4*)&g_I2U[(size_t)it * D + off];
    float* dstU = &user_out[(size_t)u * D + off];
    asm volatile("red.global.add.v4.f32 [%0], {%1,%2,%3,%4};" ::
        "l"(dstU),
        "f"(mi.x + bi.x), "f"(mi.y + bi.y), "f"(mi.z + bi.z), "f"(mi.w + bi.w)
        : "memory");
}

extern "C" void kernel_launch(void* const* d_in, const int* in_sizes, int n_in,
                              void* d_out, int out_size)
{
    const float* user_feat = (const float*)d_in[0];
    const float* item_feat = (const float*)d_in[1];
    const int*   edges     = (const int*)d_in[2];
    const float* W_user = (const float*)d_in[3];
    const float* b_user = (const float*)d_in[4];
    const float* W_item = (const float*)d_in[5];
    const float* b_item = (const float*)d_in[6];
    const float* W_u2i  = (const float*)d_in[7];
    const float* b_u2i  = (const float*)d_in[8];
    const float* W_i2u  = (const float*)d_in[9];
    const float* b_i2u  = (const float*)d_in[10];

    const int nU = in_sizes[0] / D;
    const int nI = in_sizes[1] / D;
    const int E  = in_sizes[2] / 2;

    float* user_out = (float*)d_out;
    float* item_out = (float*)d_out + (size_t)nU * D;

    float* u2i_ptr = nullptr;
    float* i2u_ptr = nullptr;
    cudaGetSymbolAddress((void**)&u2i_ptr, g_U2I);
    cudaGetSymbolAddress((void**)&i2u_ptr, g_I2U);

    const int smem_bytes = (128 * 256 + TILE_ROWS * D) * sizeof(float); // 163840
    cudaFuncSetAttribute(gemm_dual, cudaFuncAttributeMaxDynamicSharedMemorySize, smem_bytes);

    const int grid_gemm = 152;  // persistent, 1 block/SM (smem-limited)

    // self-transform + message-transform for users and items (bias-free message path)
    gemm_dual<<<grid_gemm, NTHREADS, smem_bytes>>>(
        user_feat, nU, W_user, b_user, W_u2i, user_out, u2i_ptr);
    gemm_dual<<<grid_gemm, NTHREADS, smem_bytes>>>(
        item_feat, nI, W_item, b_item, W_i2u, item_out, i2u_ptr);

    // edge scatter: one warp per edge, both directions, bias folded in
    const int warps_per_block = NTHREADS / 32;
    const int grid_sc = (E + warps_per_block - 1) / warps_per_block;
    scatter_k<<<grid_sc, NTHREADS>>>(
        edges, edges + E, b_u2i, b_i2u, user_out, item_out, E);
}